// round 3
// baseline (speedup 1.0000x reference)
#include <cuda_runtime.h>
#include <cstdint>

#define NB   4
#define NH   16
#define SEQ  2048
#define DMOD 1024
#define DH   64
#define BHN  (NB * NH)        // 64
#define SL   4194304          // floats per attn slice (2048*2048)
#define PBH  131072           // floats per (bh) Q/K/V slab (2048*64)
#define NSPLIT 58             // bh 0..57 staged in d_out, 58..63 in g_tail

// Tiny scratch for the 6 tail (bh) Q/K/V slabs: 18 * 131072 floats = 9.4 MB.
static __device__ float g_tail[18 * PBH];

// ---------------------------------------------------------------------------
// Kernel 1: fused QKV projection. Y = X @ W + bias.
// Q/K/V for bh<58 -> stage (= attn + 58*SL) at which*8388608 + bh*PBH;
// bh>=58 -> g_tail at which*786432 + (bh-58)*PBH. Layout per slab: (s, d).
// ---------------------------------------------------------------------------
__global__ __launch_bounds__(256) void proj_kernel(
    const float* __restrict__ xq, const float* __restrict__ xk, const float* __restrict__ xv,
    const float* __restrict__ wq, const float* __restrict__ wk, const float* __restrict__ wv,
    const float* __restrict__ bq, const float* __restrict__ bk, const float* __restrict__ bv,
    float* __restrict__ stage)
{
    const int which = blockIdx.z;
    const float* X  = (which == 0) ? xq : (which == 1) ? xk : xv;
    const float* W  = (which == 0) ? wq : (which == 1) ? wk : wv;
    const float* Bi = (which == 0) ? bq : (which == 1) ? bk : bv;

    __shared__ float As[8][132];   // transposed A tile (padded)
    __shared__ float Bs[8][128];

    const int tid = threadIdx.x;
    const int m0 = blockIdx.y * 128;
    const int n0 = blockIdx.x * 128;
    const int ty = tid >> 4, tx = tid & 15;

    const int arow = tid >> 1;
    const int acol = (tid & 1) * 4;
    const int brow = tid >> 5;
    const int bcol = (tid & 31) * 4;

    float acc[8][8];
#pragma unroll
    for (int i = 0; i < 8; i++)
#pragma unroll
        for (int j = 0; j < 8; j++) acc[i][j] = 0.f;

    for (int k0 = 0; k0 < DMOD; k0 += 8) {
        float4 av = *(const float4*)&X[(size_t)(m0 + arow) * DMOD + k0 + acol];
        float4 bv = *(const float4*)&W[(size_t)(k0 + brow) * DMOD + n0 + bcol];
        __syncthreads();
        As[acol + 0][arow] = av.x;
        As[acol + 1][arow] = av.y;
        As[acol + 2][arow] = av.z;
        As[acol + 3][arow] = av.w;
        *(float4*)&Bs[brow][bcol] = bv;
        __syncthreads();
#pragma unroll
        for (int kk = 0; kk < 8; kk++) {
            float a[8], b[8];
            *(float4*)&a[0] = *(float4*)&As[kk][ty * 4];
            *(float4*)&a[4] = *(float4*)&As[kk][64 + ty * 4];
            *(float4*)&b[0] = *(float4*)&Bs[kk][tx * 4];
            *(float4*)&b[4] = *(float4*)&Bs[kk][64 + tx * 4];
#pragma unroll
            for (int i = 0; i < 8; i++)
#pragma unroll
                for (int j = 0; j < 8; j++)
                    acc[i][j] += a[i] * b[j];
        }
    }

    const float4 blo = *(const float4*)&Bi[n0 + tx * 4];
    const float4 bhi = *(const float4*)&Bi[n0 + 64 + tx * 4];
    const int nlo = n0 + tx * 4;
    const int nhi = n0 + 64 + tx * 4;
    const int hlo = nlo >> 6, dlo = nlo & 63;
    const int hhi = nhi >> 6, dhi = nhi & 63;

    const size_t stage_base = (size_t)which * 8388608;   // which * 2 slices
    const size_t tail_base  = (size_t)which * (6 * PBH);

#pragma unroll
    for (int i = 0; i < 8; i++) {
        const int m  = m0 + ((i < 4) ? (ty * 4 + i) : (64 + ty * 4 + i - 4));
        const int bb = m >> 11;            // batch (2048 rows each)
        const int ss = m & (SEQ - 1);
        float4 vlo = make_float4(acc[i][0] + blo.x, acc[i][1] + blo.y,
                                 acc[i][2] + blo.z, acc[i][3] + blo.w);
        float4 vhi = make_float4(acc[i][4] + bhi.x, acc[i][5] + bhi.y,
                                 acc[i][6] + bhi.z, acc[i][7] + bhi.w);
        {
            const int bh = bb * NH + hlo;
            float* dst = (bh < NSPLIT)
                ? stage + stage_base + (size_t)bh * PBH
                : g_tail + tail_base + (size_t)(bh - NSPLIT) * PBH;
            *(float4*)&dst[(size_t)ss * DH + dlo] = vlo;
        }
        {
            const int bh = bb * NH + hhi;
            float* dst = (bh < NSPLIT)
                ? stage + stage_base + (size_t)bh * PBH
                : g_tail + tail_base + (size_t)(bh - NSPLIT) * PBH;
            *(float4*)&dst[(size_t)ss * DH + dhi] = vhi;
        }
    }
}

// ---------------------------------------------------------------------------
// Kernel 2: scores = Q @ K^T / sqrt(dk), masked, written into attn slice.
// ---------------------------------------------------------------------------
__global__ __launch_bounds__(256) void scores_kernel(
    const unsigned char* __restrict__ mask, float* __restrict__ attn,
    const float* __restrict__ stage, int bh0)
{
    const int bh = bh0 + blockIdx.z;
    const float* Q = (bh < NSPLIT)
        ? stage + (size_t)bh * PBH
        : g_tail + (size_t)(bh - NSPLIT) * PBH;
    const float* K = (bh < NSPLIT)
        ? stage + 8388608 + (size_t)bh * PBH
        : g_tail + (size_t)(6 * PBH) + (size_t)(bh - NSPLIT) * PBH;
    const int b = bh >> 4;

    __shared__ float As[8][132];
    __shared__ float Bs[8][132];

    const int tid = threadIdx.x;
    const int m0 = blockIdx.y * 128;
    const int n0 = blockIdx.x * 128;
    const int ty = tid >> 4, tx = tid & 15;
    const int lrow = tid >> 1;
    const int lcol = (tid & 1) * 4;

    float acc[8][8];
#pragma unroll
    for (int i = 0; i < 8; i++)
#pragma unroll
        for (int j = 0; j < 8; j++) acc[i][j] = 0.f;

    for (int k0 = 0; k0 < DH; k0 += 8) {
        float4 av = *(const float4*)&Q[(size_t)(m0 + lrow) * DH + k0 + lcol];
        float4 bv = *(const float4*)&K[(size_t)(n0 + lrow) * DH + k0 + lcol];
        __syncthreads();
        As[lcol + 0][lrow] = av.x;
        As[lcol + 1][lrow] = av.y;
        As[lcol + 2][lrow] = av.z;
        As[lcol + 3][lrow] = av.w;
        Bs[lcol + 0][lrow] = bv.x;
        Bs[lcol + 1][lrow] = bv.y;
        Bs[lcol + 2][lrow] = bv.z;
        Bs[lcol + 3][lrow] = bv.w;
        __syncthreads();
#pragma unroll
        for (int kk = 0; kk < 8; kk++) {
            float a[8], c[8];
            *(float4*)&a[0] = *(float4*)&As[kk][ty * 4];
            *(float4*)&a[4] = *(float4*)&As[kk][64 + ty * 4];
            *(float4*)&c[0] = *(float4*)&Bs[kk][tx * 4];
            *(float4*)&c[4] = *(float4*)&Bs[kk][64 + tx * 4];
#pragma unroll
            for (int i = 0; i < 8; i++)
#pragma unroll
                for (int j = 0; j < 8; j++)
                    acc[i][j] += a[i] * c[j];
        }
    }

    const float inv_scale = 0.125f;   // 1/sqrt(64)
    const int jlo = n0 + tx * 4;
    const int jhi = n0 + 64 + tx * 4;

#pragma unroll
    for (int i = 0; i < 8; i++) {
        const int gi = m0 + ((i < 4) ? (ty * 4 + i) : (64 + ty * 4 + i - 4));
        const unsigned char* mrow = mask + ((size_t)b * SEQ + gi) * SEQ;
        float* orow = attn + ((size_t)bh * SEQ + gi) * SEQ;
        float4 vlo, vhi;
        vlo.x = mrow[jlo + 0] ? -1e9f : acc[i][0] * inv_scale;
        vlo.y = mrow[jlo + 1] ? -1e9f : acc[i][1] * inv_scale;
        vlo.z = mrow[jlo + 2] ? -1e9f : acc[i][2] * inv_scale;
        vlo.w = mrow[jlo + 3] ? -1e9f : acc[i][3] * inv_scale;
        vhi.x = mrow[jhi + 0] ? -1e9f : acc[i][4] * inv_scale;
        vhi.y = mrow[jhi + 1] ? -1e9f : acc[i][5] * inv_scale;
        vhi.z = mrow[jhi + 2] ? -1e9f : acc[i][6] * inv_scale;
        vhi.w = mrow[jhi + 3] ? -1e9f : acc[i][7] * inv_scale;
        *(float4*)&orow[jlo] = vlo;
        *(float4*)&orow[jhi] = vhi;
    }
}

// ---------------------------------------------------------------------------
// Kernel 3: in-place row softmax. 1 block (128 threads) per row.
// ---------------------------------------------------------------------------
__global__ __launch_bounds__(128) void softmax_kernel(float* __restrict__ attn,
                                                      size_t row0)
{
    const size_t row = row0 + blockIdx.x;
    float* p = attn + row * SEQ;
    const int tid = threadIdx.x;
    const int wid = tid >> 5, lane = tid & 31;

    float4 v[4];
    float mx = -3.402823466e38f;
#pragma unroll
    for (int i = 0; i < 4; i++) {
        v[i] = *(float4*)&p[i * 512 + tid * 4];
        mx = fmaxf(mx, fmaxf(fmaxf(v[i].x, v[i].y), fmaxf(v[i].z, v[i].w)));
    }
#pragma unroll
    for (int o = 16; o > 0; o >>= 1) mx = fmaxf(mx, __shfl_xor_sync(0xffffffffu, mx, o));

    __shared__ float redm[4];
    __shared__ float reds[4];
    if (lane == 0) redm[wid] = mx;
    __syncthreads();
    mx = fmaxf(fmaxf(redm[0], redm[1]), fmaxf(redm[2], redm[3]));

    float sum = 0.f;
#pragma unroll
    for (int i = 0; i < 4; i++) {
        v[i].x = __expf(v[i].x - mx);
        v[i].y = __expf(v[i].y - mx);
        v[i].z = __expf(v[i].z - mx);
        v[i].w = __expf(v[i].w - mx);
        sum += (v[i].x + v[i].y) + (v[i].z + v[i].w);
    }
#pragma unroll
    for (int o = 16; o > 0; o >>= 1) sum += __shfl_xor_sync(0xffffffffu, sum, o);
    if (lane == 0) reds[wid] = sum;
    __syncthreads();
    sum = (reds[0] + reds[1]) + (reds[2] + reds[3]);

    const float inv = 1.0f / sum;
#pragma unroll
    for (int i = 0; i < 4; i++) {
        v[i].x *= inv; v[i].y *= inv; v[i].z *= inv; v[i].w *= inv;
        *(float4*)&p[i * 512 + tid * 4] = v[i];
    }
}

// ---------------------------------------------------------------------------
// Kernel 4: context = P @ V per (bh). M-tile 128, N=64, K-tile 16.
// ---------------------------------------------------------------------------
__global__ __launch_bounds__(256) void context_kernel(
    const float* __restrict__ attn, float* __restrict__ ctx,
    const float* __restrict__ stage, int bh0)
{
    const int bh = bh0 + blockIdx.y;
    const int b = bh >> 4, h = bh & 15;
    const float* P = attn + (size_t)bh * SEQ * SEQ;
    const float* V = (bh < NSPLIT)
        ? stage + 16777216 + (size_t)bh * PBH
        : g_tail + (size_t)(12 * PBH) + (size_t)(bh - NSPLIT) * PBH;

    __shared__ float As[16][132];
    __shared__ float Bs[16][64];

    const int tid = threadIdx.x;
    const int m0 = blockIdx.x * 128;
    const int ty = tid >> 4, tx = tid & 15;
    const int arow = tid >> 1;
    const int akc  = (tid & 1) * 8;
    const int brow = tid >> 4;
    const int bcol = (tid & 15) * 4;

    float acc[8][4];
#pragma unroll
    for (int i = 0; i < 8; i++)
#pragma unroll
        for (int j = 0; j < 4; j++) acc[i][j] = 0.f;

    for (int k0 = 0; k0 < SEQ; k0 += 16) {
        float4 a0 = *(const float4*)&P[(size_t)(m0 + arow) * SEQ + k0 + akc];
        float4 a1 = *(const float4*)&P[(size_t)(m0 + arow) * SEQ + k0 + akc + 4];
        float4 bv = *(const float4*)&V[(size_t)(k0 + brow) * DH + bcol];
        __syncthreads();
        As[akc + 0][arow] = a0.x;
        As[akc + 1][arow] = a0.y;
        As[akc + 2][arow] = a0.z;
        As[akc + 3][arow] = a0.w;
        As[akc + 4][arow] = a1.x;
        As[akc + 5][arow] = a1.y;
        As[akc + 6][arow] = a1.z;
        As[akc + 7][arow] = a1.w;
        *(float4*)&Bs[brow][bcol] = bv;
        __syncthreads();
#pragma unroll
        for (int kk = 0; kk < 16; kk++) {
            float a[8], c[4];
            *(float4*)&a[0] = *(float4*)&As[kk][ty * 4];
            *(float4*)&a[4] = *(float4*)&As[kk][64 + ty * 4];
            *(float4*)&c[0] = *(float4*)&Bs[kk][tx * 4];
#pragma unroll
            for (int i = 0; i < 8; i++)
#pragma unroll
                for (int j = 0; j < 4; j++)
                    acc[i][j] += a[i] * c[j];
        }
    }

#pragma unroll
    for (int i = 0; i < 8; i++) {
        const int s = m0 + ((i < 4) ? (ty * 4 + i) : (64 + ty * 4 + i - 4));
        float4 v = make_float4(acc[i][0], acc[i][1], acc[i][2], acc[i][3]);
        *(float4*)&ctx[((size_t)b * SEQ + s) * DMOD + h * DH + tx * 4] = v;
    }
}

// ---------------------------------------------------------------------------
// Launch. Inputs: q,k,v, attn_mask, w_q,w_k,w_v, b_q,b_k,b_v.
// Output: [context (4,2048,1024) | attn (4,16,2048,2048)] fp32.
//
// Staging: Q/K/V for bh<58 live in attn slices 58..63 ("stage") until phase A
// finishes; bh>=58 live in the 9.4 MB g_tail, so phase B can overwrite the
// staged slices with the real attn output for bh 58..63.
// ---------------------------------------------------------------------------
extern "C" void kernel_launch(void* const* d_in, const int* in_sizes, int n_in,
                              void* d_out, int out_size)
{
    (void)in_sizes; (void)n_in; (void)out_size;
    const float* q  = (const float*)d_in[0];
    const float* k  = (const float*)d_in[1];
    const float* v  = (const float*)d_in[2];
    const unsigned char* mask = (const unsigned char*)d_in[3];
    const float* wq = (const float*)d_in[4];
    const float* wk = (const float*)d_in[5];
    const float* wv = (const float*)d_in[6];
    const float* bq = (const float*)d_in[7];
    const float* bk = (const float*)d_in[8];
    const float* bv = (const float*)d_in[9];

    float* ctx   = (float*)d_out;
    float* attn  = (float*)d_out + (size_t)NB * SEQ * DMOD;  // context first
    float* stage = attn + (size_t)NSPLIT * SL;               // slices 58..63

    // 1) QKV projections into staging
    {
        dim3 grid(DMOD / 128, (NB * SEQ) / 128, 3);
        proj_kernel<<<grid, 256>>>(q, k, v, wq, wk, wv, bq, bk, bv, stage);
    }
    // Phase A: bh 0..57
    {
        dim3 grid(SEQ / 128, SEQ / 128, NSPLIT);
        scores_kernel<<<grid, 256>>>(mask, attn, stage, 0);
    }
    softmax_kernel<<<NSPLIT * SEQ, 128>>>(attn, 0);
    {
        dim3 grid(SEQ / 128, NSPLIT);
        context_kernel<<<grid, 256>>>(attn, ctx, stage, 0);
    }
    // Phase B: bh 58..63 (QKV in g_tail; staged slices now reusable)
    {
        dim3 grid(SEQ / 128, SEQ / 128, BHN - NSPLIT);
        scores_kernel<<<grid, 256>>>(mask, attn, stage, NSPLIT);
    }
    softmax_kernel<<<(BHN - NSPLIT) * SEQ, 128>>>(attn, (size_t)NSPLIT * SEQ);
    {
        dim3 grid(SEQ / 128, BHN - NSPLIT);
        context_kernel<<<grid, 256>>>(attn, ctx, stage, NSPLIT);
    }
}

// round 8
// speedup vs baseline: 1.5172x; 1.5172x over previous
#include <cuda_runtime.h>
#include <cstdint>

#define NB   4
#define NH   16
#define SEQ  2048
#define DMOD 1024
#define DH   64
#define BHN  (NB * NH)        // 64
#define SL   4194304          // floats per attn slice (2048*2048)
#define PBH  131072           // floats per (bh) Q/K/V slab (2048*64)
#define NSPLIT 58             // bh 0..57 staged in d_out, 58..63 in g_tail

// Tiny scratch for the 6 tail (bh) Q/K/V slabs: 18 * 131072 floats = 9.4 MB.
static __device__ float g_tail[18 * PBH];

// ---------------------------------------------------------------------------
// tf32 helpers
// ---------------------------------------------------------------------------
__device__ __forceinline__ uint32_t f2tf(float f) {
    uint32_t u;
    asm("cvt.rna.tf32.f32 %0, %1;" : "=r"(u) : "f"(f));
    return u;
}

__device__ __forceinline__ void mma_tf32(float* c, const uint32_t* a, const uint32_t* b) {
    asm volatile(
        "mma.sync.aligned.m16n8k8.row.col.f32.tf32.tf32.f32 "
        "{%0,%1,%2,%3}, {%4,%5,%6,%7}, {%8,%9}, {%0,%1,%2,%3};"
        : "+f"(c[0]), "+f"(c[1]), "+f"(c[2]), "+f"(c[3])
        : "r"(a[0]), "r"(a[1]), "r"(a[2]), "r"(a[3]), "r"(b[0]), "r"(b[1]));
}

// ---------------------------------------------------------------------------
// Kernel 1: fused QKV projection via tf32 mma. Y = X @ W + bias.
// Block 128x128, K-tile 16, 8 warps (2x4), warp tile 64x32.
// Output scatter to (bh, s, d) slabs in stage/g_tail.
// ---------------------------------------------------------------------------
__global__ __launch_bounds__(256) void proj_kernel(
    const float* __restrict__ xq, const float* __restrict__ xk, const float* __restrict__ xv,
    const float* __restrict__ wq, const float* __restrict__ wk, const float* __restrict__ wv,
    const float* __restrict__ bq, const float* __restrict__ bk, const float* __restrict__ bv,
    float* __restrict__ stage)
{
    const int which = blockIdx.z;
    const float* X  = (which == 0) ? xq : (which == 1) ? xk : xv;
    const float* W  = (which == 0) ? wq : (which == 1) ? wk : wv;
    const float* Bi = (which == 0) ? bq : (which == 1) ? bk : bv;

    __shared__ uint32_t As[16][132];   // k-major, padded: As[k][m]
    __shared__ uint32_t Bs[16][132];   // k-major: Bs[k][n]

    const int tid  = threadIdx.x;
    const int warp = tid >> 5;
    const int lane = tid & 31;
    const int gr   = lane >> 2;        // group row
    const int tg   = lane & 3;         // thread-in-group

    const int m0 = blockIdx.y * 128;
    const int n0 = blockIdx.x * 128;
    const int warp_m = (warp >> 2) * 64;
    const int warp_n = (warp & 3) * 32;

    const int a_r = tid >> 1;              // 0..127
    const int a_kc = (tid & 1) * 8;        // 0 or 8
    const int b_kr = tid >> 4;             // 0..15
    const int b_nc = (tid & 15) * 8;       // 0..120

    float acc[4][4][4];
#pragma unroll
    for (int mt = 0; mt < 4; mt++)
#pragma unroll
        for (int nt = 0; nt < 4; nt++)
#pragma unroll
            for (int r = 0; r < 4; r++) acc[mt][nt][r] = 0.f;

    for (int k0 = 0; k0 < DMOD; k0 += 16) {
        float4 x0 = *(const float4*)&X[(size_t)(m0 + a_r) * DMOD + k0 + a_kc];
        float4 x1 = *(const float4*)&X[(size_t)(m0 + a_r) * DMOD + k0 + a_kc + 4];
        float4 w0 = *(const float4*)&W[(size_t)(k0 + b_kr) * DMOD + n0 + b_nc];
        float4 w1 = *(const float4*)&W[(size_t)(k0 + b_kr) * DMOD + n0 + b_nc + 4];
        __syncthreads();
        As[a_kc + 0][a_r] = f2tf(x0.x);
        As[a_kc + 1][a_r] = f2tf(x0.y);
        As[a_kc + 2][a_r] = f2tf(x0.z);
        As[a_kc + 3][a_r] = f2tf(x0.w);
        As[a_kc + 4][a_r] = f2tf(x1.x);
        As[a_kc + 5][a_r] = f2tf(x1.y);
        As[a_kc + 6][a_r] = f2tf(x1.z);
        As[a_kc + 7][a_r] = f2tf(x1.w);
        Bs[b_kr][b_nc + 0] = f2tf(w0.x);
        Bs[b_kr][b_nc + 1] = f2tf(w0.y);
        Bs[b_kr][b_nc + 2] = f2tf(w0.z);
        Bs[b_kr][b_nc + 3] = f2tf(w0.w);
        Bs[b_kr][b_nc + 4] = f2tf(w1.x);
        Bs[b_kr][b_nc + 5] = f2tf(w1.y);
        Bs[b_kr][b_nc + 6] = f2tf(w1.z);
        Bs[b_kr][b_nc + 7] = f2tf(w1.w);
        __syncthreads();

#pragma unroll
        for (int kk = 0; kk < 16; kk += 8) {
            uint32_t af[4][4], bf[4][2];
#pragma unroll
            for (int mt = 0; mt < 4; mt++) {
                const int mm = warp_m + mt * 16 + gr;
                af[mt][0] = As[kk + tg][mm];
                af[mt][1] = As[kk + tg][mm + 8];
                af[mt][2] = As[kk + tg + 4][mm];
                af[mt][3] = As[kk + tg + 4][mm + 8];
            }
#pragma unroll
            for (int nt = 0; nt < 4; nt++) {
                const int nn = warp_n + nt * 8 + gr;
                bf[nt][0] = Bs[kk + tg][nn];
                bf[nt][1] = Bs[kk + tg + 4][nn];
            }
#pragma unroll
            for (int mt = 0; mt < 4; mt++)
#pragma unroll
                for (int nt = 0; nt < 4; nt++)
                    mma_tf32(acc[mt][nt], af[mt], bf[nt]);
        }
    }

    // Epilogue: bias + scatter. Head and batch are fixed per warp/block.
    const int h  = (n0 + warp_n) >> 6;          // 0..15
    const int bb = m0 >> 11;                    // batch
    const int bh = bb * NH + h;
    const int d_base = ((n0 + warp_n) & 63);
    const int ss_base = (m0 & (SEQ - 1)) + warp_m;

    float* dst = (bh < NSPLIT)
        ? stage + (size_t)which * 8388608 + (size_t)bh * PBH
        : g_tail + (size_t)which * (6 * PBH) + (size_t)(bh - NSPLIT) * PBH;

#pragma unroll
    for (int nt = 0; nt < 4; nt++) {
        const int ncol = n0 + warp_n + nt * 8 + 2 * tg;
        const float bias0 = Bi[ncol];
        const float bias1 = Bi[ncol + 1];
        const int d = d_base + nt * 8 + 2 * tg;
#pragma unroll
        for (int mt = 0; mt < 4; mt++) {
            const int s0 = ss_base + mt * 16 + gr;
            float2 v0 = make_float2(acc[mt][nt][0] + bias0, acc[mt][nt][1] + bias1);
            float2 v1 = make_float2(acc[mt][nt][2] + bias0, acc[mt][nt][3] + bias1);
            *(float2*)&dst[(size_t)s0 * DH + d] = v0;
            *(float2*)&dst[(size_t)(s0 + 8) * DH + d] = v1;
        }
    }
}

// ---------------------------------------------------------------------------
// Kernel 2: scores = Q @ K^T / 8, masked, tf32 mma. Block 128x128, K=64.
// ---------------------------------------------------------------------------
__global__ __launch_bounds__(256) void scores_kernel(
    const unsigned char* __restrict__ mask, float* __restrict__ attn,
    const float* __restrict__ stage, int bh0)
{
    const int bh = bh0 + blockIdx.z;
    const float* Q = (bh < NSPLIT)
        ? stage + (size_t)bh * PBH
        : g_tail + (size_t)(bh - NSPLIT) * PBH;
    const float* K = (bh < NSPLIT)
        ? stage + 8388608 + (size_t)bh * PBH
        : g_tail + (size_t)(6 * PBH) + (size_t)(bh - NSPLIT) * PBH;
    const int b = bh >> 4;

    __shared__ uint32_t As[16][132];
    __shared__ uint32_t Bs[16][132];

    const int tid  = threadIdx.x;
    const int warp = tid >> 5;
    const int lane = tid & 31;
    const int gr   = lane >> 2;
    const int tg   = lane & 3;

    const int m0 = blockIdx.y * 128;
    const int n0 = blockIdx.x * 128;
    const int warp_m = (warp >> 2) * 64;
    const int warp_n = (warp & 3) * 32;

    const int l_r  = tid >> 1;
    const int l_kc = (tid & 1) * 8;

    float acc[4][4][4];
#pragma unroll
    for (int mt = 0; mt < 4; mt++)
#pragma unroll
        for (int nt = 0; nt < 4; nt++)
#pragma unroll
            for (int r = 0; r < 4; r++) acc[mt][nt][r] = 0.f;

    for (int k0 = 0; k0 < DH; k0 += 16) {
        float4 q0 = *(const float4*)&Q[(size_t)(m0 + l_r) * DH + k0 + l_kc];
        float4 q1 = *(const float4*)&Q[(size_t)(m0 + l_r) * DH + k0 + l_kc + 4];
        float4 c0 = *(const float4*)&K[(size_t)(n0 + l_r) * DH + k0 + l_kc];
        float4 c1 = *(const float4*)&K[(size_t)(n0 + l_r) * DH + k0 + l_kc + 4];
        __syncthreads();
        As[l_kc + 0][l_r] = f2tf(q0.x);
        As[l_kc + 1][l_r] = f2tf(q0.y);
        As[l_kc + 2][l_r] = f2tf(q0.z);
        As[l_kc + 3][l_r] = f2tf(q0.w);
        As[l_kc + 4][l_r] = f2tf(q1.x);
        As[l_kc + 5][l_r] = f2tf(q1.y);
        As[l_kc + 6][l_r] = f2tf(q1.z);
        As[l_kc + 7][l_r] = f2tf(q1.w);
        Bs[l_kc + 0][l_r] = f2tf(c0.x);
        Bs[l_kc + 1][l_r] = f2tf(c0.y);
        Bs[l_kc + 2][l_r] = f2tf(c0.z);
        Bs[l_kc + 3][l_r] = f2tf(c0.w);
        Bs[l_kc + 4][l_r] = f2tf(c1.x);
        Bs[l_kc + 5][l_r] = f2tf(c1.y);
        Bs[l_kc + 6][l_r] = f2tf(c1.z);
        Bs[l_kc + 7][l_r] = f2tf(c1.w);
        __syncthreads();

#pragma unroll
        for (int kk = 0; kk < 16; kk += 8) {
            uint32_t af[4][4], bf[4][2];
#pragma unroll
            for (int mt = 0; mt < 4; mt++) {
                const int mm = warp_m + mt * 16 + gr;
                af[mt][0] = As[kk + tg][mm];
                af[mt][1] = As[kk + tg][mm + 8];
                af[mt][2] = As[kk + tg + 4][mm];
                af[mt][3] = As[kk + tg + 4][mm + 8];
            }
#pragma unroll
            for (int nt = 0; nt < 4; nt++) {
                const int nn = warp_n + nt * 8 + gr;
                bf[nt][0] = Bs[kk + tg][nn];
                bf[nt][1] = Bs[kk + tg + 4][nn];
            }
#pragma unroll
            for (int mt = 0; mt < 4; mt++)
#pragma unroll
                for (int nt = 0; nt < 4; nt++)
                    mma_tf32(acc[mt][nt], af[mt], bf[nt]);
        }
    }

    const float inv_scale = 0.125f;
#pragma unroll
    for (int mt = 0; mt < 4; mt++) {
        const int gi0 = m0 + warp_m + mt * 16 + gr;
        const int gi1 = gi0 + 8;
        const unsigned char* mr0 = mask + ((size_t)b * SEQ + gi0) * SEQ;
        const unsigned char* mr1 = mask + ((size_t)b * SEQ + gi1) * SEQ;
        float* or0 = attn + ((size_t)bh * SEQ + gi0) * SEQ;
        float* or1 = attn + ((size_t)bh * SEQ + gi1) * SEQ;
#pragma unroll
        for (int nt = 0; nt < 4; nt++) {
            const int cj = n0 + warp_n + nt * 8 + 2 * tg;
            float2 v0, v1;
            v0.x = mr0[cj + 0] ? -1e9f : acc[mt][nt][0] * inv_scale;
            v0.y = mr0[cj + 1] ? -1e9f : acc[mt][nt][1] * inv_scale;
            v1.x = mr1[cj + 0] ? -1e9f : acc[mt][nt][2] * inv_scale;
            v1.y = mr1[cj + 1] ? -1e9f : acc[mt][nt][3] * inv_scale;
            *(float2*)&or0[cj] = v0;
            *(float2*)&or1[cj] = v1;
        }
    }
}

// ---------------------------------------------------------------------------
// Kernel 3: in-place row softmax. 1 block (128 threads) per row.
// ---------------------------------------------------------------------------
__global__ __launch_bounds__(128) void softmax_kernel(float* __restrict__ attn,
                                                      size_t row0)
{
    const size_t row = row0 + blockIdx.x;
    float* p = attn + row * SEQ;
    const int tid = threadIdx.x;
    const int wid = tid >> 5, lane = tid & 31;

    float4 v[4];
    float mx = -3.402823466e38f;
#pragma unroll
    for (int i = 0; i < 4; i++) {
        v[i] = *(float4*)&p[i * 512 + tid * 4];
        mx = fmaxf(mx, fmaxf(fmaxf(v[i].x, v[i].y), fmaxf(v[i].z, v[i].w)));
    }
#pragma unroll
    for (int o = 16; o > 0; o >>= 1) mx = fmaxf(mx, __shfl_xor_sync(0xffffffffu, mx, o));

    __shared__ float redm[4];
    __shared__ float reds[4];
    if (lane == 0) redm[wid] = mx;
    __syncthreads();
    mx = fmaxf(fmaxf(redm[0], redm[1]), fmaxf(redm[2], redm[3]));

    float sum = 0.f;
#pragma unroll
    for (int i = 0; i < 4; i++) {
        v[i].x = __expf(v[i].x - mx);
        v[i].y = __expf(v[i].y - mx);
        v[i].z = __expf(v[i].z - mx);
        v[i].w = __expf(v[i].w - mx);
        sum += (v[i].x + v[i].y) + (v[i].z + v[i].w);
    }
#pragma unroll
    for (int o = 16; o > 0; o >>= 1) sum += __shfl_xor_sync(0xffffffffu, sum, o);
    if (lane == 0) reds[wid] = sum;
    __syncthreads();
    sum = (reds[0] + reds[1]) + (reds[2] + reds[3]);

    const float inv = 1.0f / sum;
#pragma unroll
    for (int i = 0; i < 4; i++) {
        v[i].x *= inv; v[i].y *= inv; v[i].z *= inv; v[i].w *= inv;
        *(float4*)&p[i * 512 + tid * 4] = v[i];
    }
}

// ---------------------------------------------------------------------------
// Kernel 4: context = P @ V per (bh), tf32 mma. Block 256x64, K-tile 16,
// 8 warps (4x2), warp tile 64x32.
// ---------------------------------------------------------------------------
__global__ __launch_bounds__(256) void context_kernel(
    const float* __restrict__ attn, float* __restrict__ ctx,
    const float* __restrict__ stage, int bh0)
{
    const int bh = bh0 + blockIdx.y;
    const int b = bh >> 4, h = bh & 15;
    const float* P = attn + (size_t)bh * SEQ * SEQ;
    const float* V = (bh < NSPLIT)
        ? stage + 16777216 + (size_t)bh * PBH
        : g_tail + (size_t)(12 * PBH) + (size_t)(bh - NSPLIT) * PBH;

    __shared__ uint32_t As[16][260];   // As[k][m], m-tile 256
    __shared__ uint32_t Bs[16][68];    // Bs[k][n], n = 64

    const int tid  = threadIdx.x;
    const int warp = tid >> 5;
    const int lane = tid & 31;
    const int gr   = lane >> 2;
    const int tg   = lane & 3;

    const int m0 = blockIdx.x * 256;
    const int warp_m = (warp >> 1) * 64;
    const int warp_n = (warp & 1) * 32;

    const int a_sub = tid >> 2;          // 0..63 row within 64-row group
    const int a_kc  = (tid & 3) * 4;     // 0,4,8,12
    const int b_kr  = tid >> 4;          // 0..15
    const int b_nc  = (tid & 15) * 4;    // 0..60

    float acc[4][4][4];
#pragma unroll
    for (int mt = 0; mt < 4; mt++)
#pragma unroll
        for (int nt = 0; nt < 4; nt++)
#pragma unroll
            for (int r = 0; r < 4; r++) acc[mt][nt][r] = 0.f;

    for (int k0 = 0; k0 < SEQ; k0 += 16) {
        float4 pv[4];
#pragma unroll
        for (int r = 0; r < 4; r++) {
            const int row = r * 64 + a_sub;
            pv[r] = *(const float4*)&P[(size_t)(m0 + row) * SEQ + k0 + a_kc];
        }
        float4 vv = *(const float4*)&V[(size_t)(k0 + b_kr) * DH + b_nc];
        __syncthreads();
#pragma unroll
        for (int r = 0; r < 4; r++) {
            const int row = r * 64 + a_sub;
            As[a_kc + 0][row] = f2tf(pv[r].x);
            As[a_kc + 1][row] = f2tf(pv[r].y);
            As[a_kc + 2][row] = f2tf(pv[r].z);
            As[a_kc + 3][row] = f2tf(pv[r].w);
        }
        Bs[b_kr][b_nc + 0] = f2tf(vv.x);
        Bs[b_kr][b_nc + 1] = f2tf(vv.y);
        Bs[b_kr][b_nc + 2] = f2tf(vv.z);
        Bs[b_kr][b_nc + 3] = f2tf(vv.w);
        __syncthreads();

#pragma unroll
        for (int kk = 0; kk < 16; kk += 8) {
            uint32_t af[4][4], bf[4][2];
#pragma unroll
            for (int mt = 0; mt < 4; mt++) {
                const int mm = warp_m + mt * 16 + gr;
                af[mt][0] = As[kk + tg][mm];
                af[mt][1] = As[kk + tg][mm + 8];
                af[mt][2] = As[kk + tg + 4][mm];
                af[mt][3] = As[kk + tg + 4][mm + 8];
            }
#pragma unroll
            for (int nt = 0; nt < 4; nt++) {
                const int nn = warp_n + nt * 8 + gr;
                bf[nt][0] = Bs[kk + tg][nn];
                bf[nt][1] = Bs[kk + tg + 4][nn];
            }
#pragma unroll
            for (int mt = 0; mt < 4; mt++)
#pragma unroll
                for (int nt = 0; nt < 4; nt++)
                    mma_tf32(acc[mt][nt], af[mt], bf[nt]);
        }
    }

#pragma unroll
    for (int mt = 0; mt < 4; mt++) {
        const int s0 = m0 + warp_m + mt * 16 + gr;
        const int s1 = s0 + 8;
#pragma unroll
        for (int nt = 0; nt < 4; nt++) {
            const int d = warp_n + nt * 8 + 2 * tg;
            float2 v0 = make_float2(acc[mt][nt][0], acc[mt][nt][1]);
            float2 v1 = make_float2(acc[mt][nt][2], acc[mt][nt][3]);
            *(float2*)&ctx[((size_t)b * SEQ + s0) * DMOD + h * DH + d] = v0;
            *(float2*)&ctx[((size_t)b * SEQ + s1) * DMOD + h * DH + d] = v1;
        }
    }
}

// ---------------------------------------------------------------------------
// Launch. Inputs: q,k,v, attn_mask, w_q,w_k,w_v, b_q,b_k,b_v.
// Output: [context (4,2048,1024) | attn (4,16,2048,2048)] fp32.
// ---------------------------------------------------------------------------
extern "C" void kernel_launch(void* const* d_in, const int* in_sizes, int n_in,
                              void* d_out, int out_size)
{
    (void)in_sizes; (void)n_in; (void)out_size;
    const float* q  = (const float*)d_in[0];
    const float* k  = (const float*)d_in[1];
    const float* v  = (const float*)d_in[2];
    const unsigned char* mask = (const unsigned char*)d_in[3];
    const float* wq = (const float*)d_in[4];
    const float* wk = (const float*)d_in[5];
    const float* wv = (const float*)d_in[6];
    const float* bq = (const float*)d_in[7];
    const float* bk = (const float*)d_in[8];
    const float* bv = (const float*)d_in[9];

    float* ctx   = (float*)d_out;
    float* attn  = (float*)d_out + (size_t)NB * SEQ * DMOD;  // context first
    float* stage = attn + (size_t)NSPLIT * SL;               // slices 58..63

    // 1) QKV projections into staging
    {
        dim3 grid(DMOD / 128, (NB * SEQ) / 128, 3);
        proj_kernel<<<grid, 256>>>(q, k, v, wq, wk, wv, bq, bk, bv, stage);
    }
    // Phase A: bh 0..57
    {
        dim3 grid(SEQ / 128, SEQ / 128, NSPLIT);
        scores_kernel<<<grid, 256>>>(mask, attn, stage, 0);
    }
    softmax_kernel<<<NSPLIT * SEQ, 128>>>(attn, 0);
    {
        dim3 grid(SEQ / 256, NSPLIT);
        context_kernel<<<grid, 256>>>(attn, ctx, stage, 0);
    }
    // Phase B: bh 58..63 (QKV in g_tail; staged slices now reusable)
    {
        dim3 grid(SEQ / 128, SEQ / 128, BHN - NSPLIT);
        scores_kernel<<<grid, 256>>>(mask, attn, stage, NSPLIT);
    }
    softmax_kernel<<<(BHN - NSPLIT) * SEQ, 128>>>(attn, (size_t)NSPLIT * SEQ);
    {
        dim3 grid(SEQ / 256, BHN - NSPLIT);
        context_kernel<<<grid, 256>>>(attn, ctx, stage, NSPLIT);
    }
}

// round 9
// speedup vs baseline: 1.6801x; 1.1073x over previous
#include <cuda_runtime.h>
#include <cstdint>

#define NB   4
#define NH   16
#define SEQ  2048
#define DMOD 1024
#define DH   64
#define BHN  (NB * NH)        // 64
#define SL   4194304          // floats per attn slice (2048*2048)
#define PBH  131072           // floats per (bh) Q/K/V slab (2048*64)
#define NSPLIT 58             // bh 0..57 staged in d_out, 58..63 in g_tail

// Scratch: 6 tail (bh) Q/K/V slabs (9.4 MB) + row sums (0.5 MB).
static __device__ float g_tail[18 * PBH];
static __device__ float g_sums[(size_t)BHN * SEQ];

// ---------------------------------------------------------------------------
// tf32 helpers
// ---------------------------------------------------------------------------
__device__ __forceinline__ uint32_t f2tf(float f) {
    uint32_t u;
    asm("cvt.rna.tf32.f32 %0, %1;" : "=r"(u) : "f"(f));
    return u;
}

__device__ __forceinline__ void mma_tf32(float* c, const uint32_t* a, const uint32_t* b) {
    asm volatile(
        "mma.sync.aligned.m16n8k8.row.col.f32.tf32.tf32.f32 "
        "{%0,%1,%2,%3}, {%4,%5,%6,%7}, {%8,%9}, {%0,%1,%2,%3};"
        : "+f"(c[0]), "+f"(c[1]), "+f"(c[2]), "+f"(c[3])
        : "r"(a[0]), "r"(a[1]), "r"(a[2]), "r"(a[3]), "r"(b[0]), "r"(b[1]));
}

// ---------------------------------------------------------------------------
// Kernel 1: fused QKV projection via tf32 mma (unchanged from R8, works).
// ---------------------------------------------------------------------------
__global__ __launch_bounds__(256) void proj_kernel(
    const float* __restrict__ xq, const float* __restrict__ xk, const float* __restrict__ xv,
    const float* __restrict__ wq, const float* __restrict__ wk, const float* __restrict__ wv,
    const float* __restrict__ bq, const float* __restrict__ bk, const float* __restrict__ bv,
    float* __restrict__ stage)
{
    const int which = blockIdx.z;
    const float* X  = (which == 0) ? xq : (which == 1) ? xk : xv;
    const float* W  = (which == 0) ? wq : (which == 1) ? wk : wv;
    const float* Bi = (which == 0) ? bq : (which == 1) ? bk : bv;

    __shared__ uint32_t As[16][136];   // pad 136: bank = 8*tg + gr, conflict-free
    __shared__ uint32_t Bs[16][136];

    const int tid  = threadIdx.x;
    const int warp = tid >> 5;
    const int lane = tid & 31;
    const int gr   = lane >> 2;
    const int tg   = lane & 3;

    const int m0 = blockIdx.y * 128;
    const int n0 = blockIdx.x * 128;
    const int warp_m = (warp >> 2) * 64;
    const int warp_n = (warp & 3) * 32;

    const int a_r = tid >> 1;
    const int a_kc = (tid & 1) * 8;
    const int b_kr = tid >> 4;
    const int b_nc = (tid & 15) * 8;

    float acc[4][4][4];
#pragma unroll
    for (int mt = 0; mt < 4; mt++)
#pragma unroll
        for (int nt = 0; nt < 4; nt++)
#pragma unroll
            for (int r = 0; r < 4; r++) acc[mt][nt][r] = 0.f;

    for (int k0 = 0; k0 < DMOD; k0 += 16) {
        float4 x0 = *(const float4*)&X[(size_t)(m0 + a_r) * DMOD + k0 + a_kc];
        float4 x1 = *(const float4*)&X[(size_t)(m0 + a_r) * DMOD + k0 + a_kc + 4];
        float4 w0 = *(const float4*)&W[(size_t)(k0 + b_kr) * DMOD + n0 + b_nc];
        float4 w1 = *(const float4*)&W[(size_t)(k0 + b_kr) * DMOD + n0 + b_nc + 4];
        __syncthreads();
        As[a_kc + 0][a_r] = f2tf(x0.x);
        As[a_kc + 1][a_r] = f2tf(x0.y);
        As[a_kc + 2][a_r] = f2tf(x0.z);
        As[a_kc + 3][a_r] = f2tf(x0.w);
        As[a_kc + 4][a_r] = f2tf(x1.x);
        As[a_kc + 5][a_r] = f2tf(x1.y);
        As[a_kc + 6][a_r] = f2tf(x1.z);
        As[a_kc + 7][a_r] = f2tf(x1.w);
        Bs[b_kr][b_nc + 0] = f2tf(w0.x);
        Bs[b_kr][b_nc + 1] = f2tf(w0.y);
        Bs[b_kr][b_nc + 2] = f2tf(w0.z);
        Bs[b_kr][b_nc + 3] = f2tf(w0.w);
        Bs[b_kr][b_nc + 4] = f2tf(w1.x);
        Bs[b_kr][b_nc + 5] = f2tf(w1.y);
        Bs[b_kr][b_nc + 6] = f2tf(w1.z);
        Bs[b_kr][b_nc + 7] = f2tf(w1.w);
        __syncthreads();

#pragma unroll
        for (int kk = 0; kk < 16; kk += 8) {
            uint32_t af[4][4], bf[4][2];
#pragma unroll
            for (int mt = 0; mt < 4; mt++) {
                const int mm = warp_m + mt * 16 + gr;
                af[mt][0] = As[kk + tg][mm];
                af[mt][1] = As[kk + tg][mm + 8];
                af[mt][2] = As[kk + tg + 4][mm];
                af[mt][3] = As[kk + tg + 4][mm + 8];
            }
#pragma unroll
            for (int nt = 0; nt < 4; nt++) {
                const int nn = warp_n + nt * 8 + gr;
                bf[nt][0] = Bs[kk + tg][nn];
                bf[nt][1] = Bs[kk + tg + 4][nn];
            }
#pragma unroll
            for (int mt = 0; mt < 4; mt++)
#pragma unroll
                for (int nt = 0; nt < 4; nt++)
                    mma_tf32(acc[mt][nt], af[mt], bf[nt]);
        }
    }

    const int h  = (n0 + warp_n) >> 6;
    const int bb = m0 >> 11;
    const int bh = bb * NH + h;
    const int d_base = ((n0 + warp_n) & 63);
    const int ss_base = (m0 & (SEQ - 1)) + warp_m;

    float* dst = (bh < NSPLIT)
        ? stage + (size_t)which * 8388608 + (size_t)bh * PBH
        : g_tail + (size_t)which * (6 * PBH) + (size_t)(bh - NSPLIT) * PBH;

#pragma unroll
    for (int nt = 0; nt < 4; nt++) {
        const int ncol = n0 + warp_n + nt * 8 + 2 * tg;
        const float bias0 = Bi[ncol];
        const float bias1 = Bi[ncol + 1];
        const int d = d_base + nt * 8 + 2 * tg;
#pragma unroll
        for (int mt = 0; mt < 4; mt++) {
            const int s0 = ss_base + mt * 16 + gr;
            float2 v0 = make_float2(acc[mt][nt][0] + bias0, acc[mt][nt][1] + bias1);
            float2 v1 = make_float2(acc[mt][nt][2] + bias0, acc[mt][nt][3] + bias1);
            *(float2*)&dst[(size_t)s0 * DH + d] = v0;
            *(float2*)&dst[(size_t)(s0 + 8) * DH + d] = v1;
        }
    }
}

// ---------------------------------------------------------------------------
// Kernel 2: FUSED attention. Per block: one bh, 128 q-rows.
// S = QK^T/8 (masked) -> p = exp(S) -> attn (unnormalized) + rowsum;
// ctx = (p @ V) * inv_sum. Q in registers; K/V tiles in smem.
// Warp w owns q-rows w*16..w*16+15, full 128-col key tiles.
// smem: Qs[128][68] | Ks[128][68] | Vs[128][72]  (104 KB dynamic)
// ---------------------------------------------------------------------------
#define QS_STRIDE 68
#define VS_STRIDE 72
#define SMEM_WORDS (2 * 128 * QS_STRIDE + 128 * VS_STRIDE)

__global__ __launch_bounds__(256) void fused_attn_kernel(
    const unsigned char* __restrict__ mask, float* __restrict__ attn,
    float* __restrict__ ctx, const float* __restrict__ stage, int bh0)
{
    extern __shared__ uint32_t smem[];
    uint32_t* Qs = smem;                       // [128][68]
    uint32_t* Ks = smem + 128 * QS_STRIDE;     // [128][68]
    uint32_t* Vs = smem + 2 * 128 * QS_STRIDE; // [128][72]

    const int bh = bh0 + blockIdx.y;
    const int m0 = blockIdx.x * 128;
    const int b = bh >> 4, h = bh & 15;

    const float* Q = (bh < NSPLIT)
        ? stage + (size_t)bh * PBH
        : g_tail + (size_t)(bh - NSPLIT) * PBH;
    const float* K = (bh < NSPLIT)
        ? stage + 8388608 + (size_t)bh * PBH
        : g_tail + (size_t)(6 * PBH) + (size_t)(bh - NSPLIT) * PBH;
    const float* V = (bh < NSPLIT)
        ? stage + 16777216 + (size_t)bh * PBH
        : g_tail + (size_t)(12 * PBH) + (size_t)(bh - NSPLIT) * PBH;

    const int tid  = threadIdx.x;
    const int warp = tid >> 5;
    const int lane = tid & 31;
    const int gr   = lane >> 2;
    const int tg   = lane & 3;

    const int r0 = warp * 16 + gr;     // q-row (local)
    const int r1 = r0 + 8;

    // --- stage Q into smem (tf32) ---
    {
        const int qrow = tid >> 1;
        const int kc   = (tid & 1) * 32;
        const float* src = Q + (size_t)(m0 + qrow) * DH + kc;
#pragma unroll
        for (int i = 0; i < 8; i++) {
            float4 v = *(const float4*)&src[i * 4];
            uint4 u = make_uint4(f2tf(v.x), f2tf(v.y), f2tf(v.z), f2tf(v.w));
            *(uint4*)&Qs[qrow * QS_STRIDE + kc + i * 4] = u;
        }
    }
    __syncthreads();

    // --- preload Q A-fragments into registers: qf[8 k-chunks][4] ---
    uint32_t qf[8][4];
#pragma unroll
    for (int kc = 0; kc < 8; kc++) {
        qf[kc][0] = Qs[r0 * QS_STRIDE + kc * 8 + tg];
        qf[kc][1] = Qs[r1 * QS_STRIDE + kc * 8 + tg];
        qf[kc][2] = Qs[r0 * QS_STRIDE + kc * 8 + tg + 4];
        qf[kc][3] = Qs[r1 * QS_STRIDE + kc * 8 + tg + 4];
    }

    float rsum0 = 0.f, rsum1 = 0.f;
    float ctxacc[8][4];
#pragma unroll
    for (int dt = 0; dt < 8; dt++)
#pragma unroll
        for (int r = 0; r < 4; r++) ctxacc[dt][r] = 0.f;

    const unsigned char* mrow0 = mask + ((size_t)b * SEQ + m0 + r0) * SEQ;
    const unsigned char* mrow1 = mask + ((size_t)b * SEQ + m0 + r1) * SEQ;
    float* arow0 = attn + ((size_t)bh * SEQ + m0 + r0) * SEQ;
    float* arow1 = attn + ((size_t)bh * SEQ + m0 + r1) * SEQ;

    const int ld_key = tid >> 1;
    const int ld_kc  = (tid & 1) * 32;
    const int quad   = lane & ~3;

    for (int kt = 0; kt < 16; kt++) {
        // --- load K,V tiles (tf32) ---
        {
            const float* ksrc = K + (size_t)(kt * 128 + ld_key) * DH + ld_kc;
            const float* vsrc = V + (size_t)(kt * 128 + ld_key) * DH + ld_kc;
#pragma unroll
            for (int i = 0; i < 8; i++) {
                float4 kv = *(const float4*)&ksrc[i * 4];
                *(uint4*)&Ks[ld_key * QS_STRIDE + ld_kc + i * 4] =
                    make_uint4(f2tf(kv.x), f2tf(kv.y), f2tf(kv.z), f2tf(kv.w));
                float4 vv = *(const float4*)&vsrc[i * 4];
                *(uint4*)&Vs[ld_key * VS_STRIDE + ld_kc + i * 4] =
                    make_uint4(f2tf(vv.x), f2tf(vv.y), f2tf(vv.z), f2tf(vv.w));
            }
        }
        __syncthreads();

        // --- S = Q K^T for this 128x128 tile ---
        float sacc[16][4];
#pragma unroll
        for (int nt = 0; nt < 16; nt++)
#pragma unroll
            for (int r = 0; r < 4; r++) sacc[nt][r] = 0.f;

#pragma unroll
        for (int kc = 0; kc < 8; kc++) {
#pragma unroll
            for (int nt = 0; nt < 16; nt++) {
                uint32_t bf[2];
                bf[0] = Ks[(nt * 8 + gr) * QS_STRIDE + kc * 8 + tg];
                bf[1] = Ks[(nt * 8 + gr) * QS_STRIDE + kc * 8 + tg + 4];
                mma_tf32(sacc[nt], qf[kc], bf);
            }
        }

        // --- scale, mask, exp, rowsum, write unnormalized p to attn ---
        const int colb = kt * 128;
#pragma unroll
        for (int nt = 0; nt < 16; nt++) {
            const int col = colb + nt * 8 + 2 * tg;
            uchar2 mm0 = *(const uchar2*)&mrow0[col];
            uchar2 mm1 = *(const uchar2*)&mrow1[col];
            float s00 = mm0.x ? -1e9f : sacc[nt][0] * 0.125f;
            float s01 = mm0.y ? -1e9f : sacc[nt][1] * 0.125f;
            float s10 = mm1.x ? -1e9f : sacc[nt][2] * 0.125f;
            float s11 = mm1.y ? -1e9f : sacc[nt][3] * 0.125f;
            float p00 = __expf(s00), p01 = __expf(s01);
            float p10 = __expf(s10), p11 = __expf(s11);
            rsum0 += p00 + p01;
            rsum1 += p10 + p11;
            sacc[nt][0] = p00; sacc[nt][1] = p01;
            sacc[nt][2] = p10; sacc[nt][3] = p11;
            *(float2*)&arow0[col] = make_float2(p00, p01);
            *(float2*)&arow1[col] = make_float2(p10, p11);
        }

        // --- ctx += p @ V : route p C-frags -> A-frags via quad shfl ---
#pragma unroll
        for (int kc = 0; kc < 16; kc++) {
            const int srcA = quad + (tg >> 1);
            const int srcB = srcA + 2;
            float x0 = __shfl_sync(0xffffffffu, sacc[kc][0], srcA);
            float x1 = __shfl_sync(0xffffffffu, sacc[kc][1], srcA);
            float y0 = __shfl_sync(0xffffffffu, sacc[kc][0], srcB);
            float y1 = __shfl_sync(0xffffffffu, sacc[kc][1], srcB);
            float z0 = __shfl_sync(0xffffffffu, sacc[kc][2], srcA);
            float z1 = __shfl_sync(0xffffffffu, sacc[kc][3], srcA);
            float w0 = __shfl_sync(0xffffffffu, sacc[kc][2], srcB);
            float w1 = __shfl_sync(0xffffffffu, sacc[kc][3], srcB);
            uint32_t pa[4];
            pa[0] = f2tf((tg & 1) ? x1 : x0);   // (row gr,  k tg)
            pa[1] = f2tf((tg & 1) ? z1 : z0);   // (row gr+8, k tg)
            pa[2] = f2tf((tg & 1) ? y1 : y0);   // (row gr,  k tg+4)
            pa[3] = f2tf((tg & 1) ? w1 : w0);   // (row gr+8, k tg+4)
#pragma unroll
            for (int dt = 0; dt < 8; dt++) {
                uint32_t vb[2];
                vb[0] = Vs[(kc * 8 + tg) * VS_STRIDE + dt * 8 + gr];
                vb[1] = Vs[(kc * 8 + tg + 4) * VS_STRIDE + dt * 8 + gr];
                mma_tf32(ctxacc[dt], pa, vb);
            }
        }
        __syncthreads();
    }

    // --- finalize: full row sums (quad reduce), write sums, scale ctx ---
    rsum0 += __shfl_xor_sync(0xffffffffu, rsum0, 1);
    rsum0 += __shfl_xor_sync(0xffffffffu, rsum0, 2);
    rsum1 += __shfl_xor_sync(0xffffffffu, rsum1, 1);
    rsum1 += __shfl_xor_sync(0xffffffffu, rsum1, 2);
    if (tg == 0) {
        g_sums[(size_t)bh * SEQ + m0 + r0] = rsum0;
        g_sums[(size_t)bh * SEQ + m0 + r1] = rsum1;
    }
    const float inv0 = 1.0f / rsum0;
    const float inv1 = 1.0f / rsum1;

    float* crow0 = ctx + ((size_t)b * SEQ + m0 + r0) * DMOD + h * DH;
    float* crow1 = ctx + ((size_t)b * SEQ + m0 + r1) * DMOD + h * DH;
#pragma unroll
    for (int dt = 0; dt < 8; dt++) {
        const int d = dt * 8 + 2 * tg;
        *(float2*)&crow0[d] = make_float2(ctxacc[dt][0] * inv0, ctxacc[dt][1] * inv0);
        *(float2*)&crow1[d] = make_float2(ctxacc[dt][2] * inv1, ctxacc[dt][3] * inv1);
    }
}

// ---------------------------------------------------------------------------
// Kernel 3: scale attn rows by 1/rowsum. One block (256 thr) per row.
// ---------------------------------------------------------------------------
__global__ __launch_bounds__(256) void scale_kernel(float* __restrict__ attn)
{
    const size_t row = blockIdx.x;
    const float inv = 1.0f / g_sums[row];
    float* p = attn + row * SEQ;
    const int tid = threadIdx.x;
    float4 v0 = *(float4*)&p[tid * 4];
    float4 v1 = *(float4*)&p[1024 + tid * 4];
    v0.x *= inv; v0.y *= inv; v0.z *= inv; v0.w *= inv;
    v1.x *= inv; v1.y *= inv; v1.z *= inv; v1.w *= inv;
    *(float4*)&p[tid * 4] = v0;
    *(float4*)&p[1024 + tid * 4] = v1;
}

// ---------------------------------------------------------------------------
// Launch. Output: [context (4,2048,1024) | attn (4,16,2048,2048)] fp32.
// Q/K/V for bh<58 staged in attn slices 58..63; bh>=58 in g_tail.
// Phase A (bh 0..57) consumes stage; phase B (58..63) overwrites it.
// ---------------------------------------------------------------------------
extern "C" void kernel_launch(void* const* d_in, const int* in_sizes, int n_in,
                              void* d_out, int out_size)
{
    (void)in_sizes; (void)n_in; (void)out_size;
    const float* q  = (const float*)d_in[0];
    const float* k  = (const float*)d_in[1];
    const float* v  = (const float*)d_in[2];
    const unsigned char* mask = (const unsigned char*)d_in[3];
    const float* wq = (const float*)d_in[4];
    const float* wk = (const float*)d_in[5];
    const float* wv = (const float*)d_in[6];
    const float* bq = (const float*)d_in[7];
    const float* bk = (const float*)d_in[8];
    const float* bv = (const float*)d_in[9];

    float* ctx   = (float*)d_out;
    float* attn  = (float*)d_out + (size_t)NB * SEQ * DMOD;
    float* stage = attn + (size_t)NSPLIT * SL;

    const int smem_bytes = SMEM_WORDS * 4;   // 106496 B
    cudaFuncSetAttribute(fused_attn_kernel,
                         cudaFuncAttributeMaxDynamicSharedMemorySize, smem_bytes);

    // 1) QKV projections into staging
    {
        dim3 grid(DMOD / 128, (NB * SEQ) / 128, 3);
        proj_kernel<<<grid, 256>>>(q, k, v, wq, wk, wv, bq, bk, bv, stage);
    }
    // 2) Phase A: fused attention for bh 0..57
    {
        dim3 grid(SEQ / 128, NSPLIT);
        fused_attn_kernel<<<grid, 256, smem_bytes>>>(mask, attn, ctx, stage, 0);
    }
    // 3) Phase B: fused attention for bh 58..63 (QKV in g_tail)
    {
        dim3 grid(SEQ / 128, BHN - NSPLIT);
        fused_attn_kernel<<<grid, 256, smem_bytes>>>(mask, attn, ctx, stage, NSPLIT);
    }
    // 4) Normalize the attn output (all rows; sums complete after phase B)
    scale_kernel<<<BHN * SEQ, 256>>>(attn);
}